// round 2
// baseline (speedup 1.0000x reference)
#include <cuda_runtime.h>
#include <cuda_bf16.h>
#include <math_constants.h>

// ---------------------------------------------------------------------------
// Problem constants (fixed shapes per reference)
// ---------------------------------------------------------------------------
#define BATCH   4
#define SEQ     2048
#define DMODEL  1024
#define NHEADS  16
#define HDIM    64
#define MROWS   (BATCH * SEQ)       // 8192

// ---------------------------------------------------------------------------
// Scratch (static device globals -- allocation-free rule)
// ---------------------------------------------------------------------------
__device__ float g_Q[BATCH * NHEADS * SEQ * HDIM];   // [B,H,S,d]
__device__ float g_K[BATCH * NHEADS * SEQ * HDIM];
__device__ float g_V[BATCH * NHEADS * SEQ * HDIM];
__device__ float g_Z[MROWS * DMODEL];                // [B,S,H*d]

// ---------------------------------------------------------------------------
// SGEMM: C = A[M,K] @ W[K,N] + bias  (fp32, 128x128x8 tiles, 256 thr, 8x8)
// MODE 0: C row-major [M,N]
// MODE 1: permute to [B,H,S,d]: row=(b,s), col=(h,d)
// ---------------------------------------------------------------------------
template <int MODE>
__global__ void __launch_bounds__(256)
sgemm_bias(const float* __restrict__ A, const float* __restrict__ W,
           const float* __restrict__ bias, float* __restrict__ C,
           int M, int N, int K)
{
    constexpr int BM = 128, BN = 128, BK = 8;
    __shared__ float As[BK][BM];
    __shared__ float Bs[BK][BN];

    const int t  = threadIdx.x;
    const int m0 = blockIdx.y * BM;
    const int n0 = blockIdx.x * BN;
    const int ty = t >> 4;        // 0..15
    const int tx = t & 15;        // 0..15

    const int rowA = t >> 1;              // 0..127
    const int colA = (t & 1) * 4;         // 0 or 4
    const int rowB = t >> 5;              // 0..7
    const int colB = (t & 31) * 4;        // 0..124

    const float* Aptr = A + (long)(m0 + rowA) * K + colA;
    const float* Wptr = W + (long)rowB * N + n0 + colB;

    float acc[8][8];
    #pragma unroll
    for (int i = 0; i < 8; i++)
        #pragma unroll
        for (int j = 0; j < 8; j++) acc[i][j] = 0.f;

    for (int k0 = 0; k0 < K; k0 += BK) {
        float4 av = *(const float4*)(Aptr + k0);
        float4 wv = *(const float4*)(Wptr + (long)k0 * N);

        As[colA + 0][rowA] = av.x;
        As[colA + 1][rowA] = av.y;
        As[colA + 2][rowA] = av.z;
        As[colA + 3][rowA] = av.w;
        *(float4*)&Bs[rowB][colB] = wv;
        __syncthreads();

        #pragma unroll
        for (int k = 0; k < BK; k++) {
            float a[8], b[8];
            *(float4*)&a[0] = *(const float4*)&As[k][ty * 8];
            *(float4*)&a[4] = *(const float4*)&As[k][ty * 8 + 4];
            *(float4*)&b[0] = *(const float4*)&Bs[k][tx * 8];
            *(float4*)&b[4] = *(const float4*)&Bs[k][tx * 8 + 4];
            #pragma unroll
            for (int i = 0; i < 8; i++)
                #pragma unroll
                for (int j = 0; j < 8; j++)
                    acc[i][j] = fmaf(a[i], b[j], acc[i][j]);
        }
        __syncthreads();
    }

    // epilogue
    #pragma unroll
    for (int i = 0; i < 8; i++) {
        const int row = m0 + ty * 8 + i;
        #pragma unroll
        for (int jq = 0; jq < 2; jq++) {
            const int col = n0 + tx * 8 + jq * 4;
            float4 o;
            o.x = acc[i][jq * 4 + 0] + bias[col + 0];
            o.y = acc[i][jq * 4 + 1] + bias[col + 1];
            o.z = acc[i][jq * 4 + 2] + bias[col + 2];
            o.w = acc[i][jq * 4 + 3] + bias[col + 3];
            if (MODE == 0) {
                *(float4*)&C[(long)row * N + col] = o;
            } else {
                const int b = row >> 11;      // row / SEQ
                const int s = row & 2047;     // row % SEQ
                const int h = col >> 6;       // col / HDIM
                const int d = col & 63;       // col % HDIM
                *(float4*)&C[(((long)(b * NHEADS + h)) * SEQ + s) * HDIM + d] = o;
            }
        }
    }
}

// ---------------------------------------------------------------------------
// Flash attention (fp32): one CTA = (batch b, head h, 64 q-rows)
// 256 threads as 16x16 grid; each thread owns a 4x4 tile of the 64x64 score
// block and a 4(row)x4(d) tile of the output accumulator.
// Shared tiles (stride 68 to dodge bank conflicts):
//   Qt [k][q]  (transposed)  -- persistent
//   Kt [k][key](transposed)  -- reused as Pt[j][q] after scores are consumed
//   Vs [j][d]  (row-major)
// ---------------------------------------------------------------------------
#define AT_LD 68
#define ATTN_SMEM (3 * 64 * AT_LD * 4)

__global__ void __launch_bounds__(256)
attn_kernel(const float* __restrict__ Q, const float* __restrict__ K,
            const float* __restrict__ V, float* __restrict__ Z)
{
    extern __shared__ float sm[];
    float* Qt = sm;
    float* Kt = sm + 64 * AT_LD;   // doubles as Pt
    float* Vs = sm + 2 * 64 * AT_LD;

    const int t  = threadIdx.x;
    const int qb = blockIdx.x;     // 0..31
    const int h  = blockIdx.y;     // 0..15
    const int b  = blockIdx.z;     // 0..3
    const int ty = t >> 4;         // 0..15 -> q rows ty*4..ty*4+3
    const int tx = t & 15;         // 0..15 -> keys/d cols tx*4..tx*4+3

    const long base = ((long)(b * NHEADS + h)) * SEQ * HDIM;

    // ---- load Q tile transposed: Qt[k][q] ----
    {
        const int r  = t >> 2;          // 0..63 (q row)
        const int c0 = (t & 3) * 16;    // 0,16,32,48 (k col)
        const float* gq = Q + base + (long)(qb * 64 + r) * HDIM + c0;
        #pragma unroll
        for (int u = 0; u < 4; u++) {
            float4 v = *(const float4*)(gq + u * 4);
            Qt[(c0 + u * 4 + 0) * AT_LD + r] = v.x;
            Qt[(c0 + u * 4 + 1) * AT_LD + r] = v.y;
            Qt[(c0 + u * 4 + 2) * AT_LD + r] = v.z;
            Qt[(c0 + u * 4 + 3) * AT_LD + r] = v.w;
        }
    }

    float o[4][4];
    float mrow[4], lrow[4];
    #pragma unroll
    for (int i = 0; i < 4; i++) {
        mrow[i] = -CUDART_INF_F;
        lrow[i] = 0.f;
        #pragma unroll
        for (int c = 0; c < 4; c++) o[i][c] = 0.f;
    }

    for (int kb = 0; kb < SEQ / 64; kb++) {
        __syncthreads();   // prior PV reads of Kt(Pt)/Vs complete

        // ---- load K (transposed) and V (row-major) tiles ----
        {
            const int r  = t >> 2;
            const int c0 = (t & 3) * 16;
            const float* gk = K + base + (long)(kb * 64 + r) * HDIM + c0;
            const float* gv = V + base + (long)(kb * 64 + r) * HDIM + c0;
            #pragma unroll
            for (int u = 0; u < 4; u++) {
                float4 kv = *(const float4*)(gk + u * 4);
                Kt[(c0 + u * 4 + 0) * AT_LD + r] = kv.x;
                Kt[(c0 + u * 4 + 1) * AT_LD + r] = kv.y;
                Kt[(c0 + u * 4 + 2) * AT_LD + r] = kv.z;
                Kt[(c0 + u * 4 + 3) * AT_LD + r] = kv.w;
                float4 vv = *(const float4*)(gv + u * 4);
                *(float4*)&Vs[r * AT_LD + c0 + u * 4] = vv;
            }
        }
        __syncthreads();

        // ---- scores: S = Q @ K^T (64x64x64 mini-GEMM) ----
        float s[4][4];
        #pragma unroll
        for (int i = 0; i < 4; i++)
            #pragma unroll
            for (int j = 0; j < 4; j++) s[i][j] = 0.f;

        #pragma unroll 8
        for (int k = 0; k < HDIM; k++) {
            float4 a  = *(const float4*)&Qt[k * AT_LD + ty * 4];
            float4 kk = *(const float4*)&Kt[k * AT_LD + tx * 4];
            float av[4] = {a.x, a.y, a.z, a.w};
            float bv[4] = {kk.x, kk.y, kk.z, kk.w};
            #pragma unroll
            for (int i = 0; i < 4; i++)
                #pragma unroll
                for (int j = 0; j < 4; j++)
                    s[i][j] = fmaf(av[i], bv[j], s[i][j]);
        }

        // ---- online softmax (rows reduced across the 16 tx lanes) ----
        float alpha[4];
        #pragma unroll
        for (int i = 0; i < 4; i++) {
            #pragma unroll
            for (int j = 0; j < 4; j++) s[i][j] *= 0.125f;  // 1/sqrt(64)
            float mx = fmaxf(fmaxf(s[i][0], s[i][1]), fmaxf(s[i][2], s[i][3]));
            #pragma unroll
            for (int msk = 1; msk < 16; msk <<= 1)
                mx = fmaxf(mx, __shfl_xor_sync(0xffffffffu, mx, msk));
            const float mnew = fmaxf(mrow[i], mx);
            alpha[i] = __expf(mrow[i] - mnew);
            float sum = 0.f;
            #pragma unroll
            for (int j = 0; j < 4; j++) {
                s[i][j] = __expf(s[i][j] - mnew);
                sum += s[i][j];
            }
            #pragma unroll
            for (int msk = 1; msk < 16; msk <<= 1)
                sum += __shfl_xor_sync(0xffffffffu, sum, msk);
            lrow[i] = lrow[i] * alpha[i] + sum;
            mrow[i] = mnew;
            #pragma unroll
            for (int c = 0; c < 4; c++) o[i][c] *= alpha[i];
        }

        __syncthreads();   // all score reads of Kt done -> safe to overwrite

        // ---- store P transposed into Kt buffer: Pt[j][q] ----
        #pragma unroll
        for (int j = 0; j < 4; j++)
            #pragma unroll
            for (int i = 0; i < 4; i++)
                Kt[(tx * 4 + j) * AT_LD + ty * 4 + i] = s[i][j];
        __syncthreads();

        // ---- O += P @ V (64x64x64 mini-GEMM) ----
        #pragma unroll 8
        for (int j = 0; j < 64; j++) {
            float4 p  = *(const float4*)&Kt[j * AT_LD + ty * 4];
            float4 vv = *(const float4*)&Vs[j * AT_LD + tx * 4];
            float pv[4] = {p.x, p.y, p.z, p.w};
            float vw[4] = {vv.x, vv.y, vv.z, vv.w};
            #pragma unroll
            for (int i = 0; i < 4; i++)
                #pragma unroll
                for (int c = 0; c < 4; c++)
                    o[i][c] = fmaf(pv[i], vw[c], o[i][c]);
        }
    }

    // ---- finalize + write Z in [B,S,H*d] layout ----
    #pragma unroll
    for (int i = 0; i < 4; i++) {
        const float inv = 1.f / lrow[i];
        const int row = qb * 64 + ty * 4 + i;
        float4 ov;
        ov.x = o[i][0] * inv;
        ov.y = o[i][1] * inv;
        ov.z = o[i][2] * inv;
        ov.w = o[i][3] * inv;
        *(float4*)&Z[((long)(b * SEQ + row)) * DMODEL + h * HDIM + tx * 4] = ov;
    }
}

// ---------------------------------------------------------------------------
// Host launcher
// ---------------------------------------------------------------------------
extern "C" void kernel_launch(void* const* d_in, const int* in_sizes, int n_in,
                              void* d_out, int out_size)
{
    const float* query = (const float*)d_in[0];
    const float* key   = (const float*)d_in[1];
    const float* value = (const float*)d_in[2];
    const float* Wq    = (const float*)d_in[3];
    const float* bq    = (const float*)d_in[4];
    const float* Wk    = (const float*)d_in[5];
    const float* bk    = (const float*)d_in[6];
    const float* Wv    = (const float*)d_in[7];
    const float* bv    = (const float*)d_in[8];
    const float* Wo    = (const float*)d_in[9];
    const float* bo    = (const float*)d_in[10];
    float* out = (float*)d_out;

    float *Qp, *Kp, *Vp, *Zp;
    cudaGetSymbolAddress((void**)&Qp, g_Q);
    cudaGetSymbolAddress((void**)&Kp, g_K);
    cudaGetSymbolAddress((void**)&Vp, g_V);
    cudaGetSymbolAddress((void**)&Zp, g_Z);

    const dim3 gg(DMODEL / 128, MROWS / 128);  // (8, 64)
    const dim3 gb(256);

    // QKV projections -> [B,H,S,d] scratch
    sgemm_bias<1><<<gg, gb>>>(query, Wq, bq, Qp, MROWS, DMODEL, DMODEL);
    sgemm_bias<1><<<gg, gb>>>(key,   Wk, bk, Kp, MROWS, DMODEL, DMODEL);
    sgemm_bias<1><<<gg, gb>>>(value, Wv, bv, Vp, MROWS, DMODEL, DMODEL);

    // Attention -> Z [B,S,H*d]
    cudaFuncSetAttribute(attn_kernel,
                         cudaFuncAttributeMaxDynamicSharedMemorySize,
                         ATTN_SMEM);
    attn_kernel<<<dim3(SEQ / 64, NHEADS, BATCH), 256, ATTN_SMEM>>>(Qp, Kp, Vp, Zp);

    // Output projection -> d_out
    sgemm_bias<0><<<gg, gb>>>(Zp, Wo, bo, out, MROWS, DMODEL, DMODEL);
}

// round 4
// speedup vs baseline: 2.5225x; 2.5225x over previous
#include <cuda_runtime.h>
#include <cuda_bf16.h>
#include <cstdint>

#define BATCH 4
#define SEQ   2048
#define DM    1024
#define NH    16
#define HD    64
#define MR    (BATCH*SEQ)   // 8192

// ---------------------------------------------------------------------------
// Scratch (__device__ globals: allocation-free rule)
// ---------------------------------------------------------------------------
__device__ __align__(128) __nv_bfloat16 g_Xc[(size_t)MR * 2048];        // [MR, hi|lo]
__device__ __align__(128) __nv_bfloat16 g_Wct[(size_t)1024 * 2048];     // [n, hi|lo over k]
__device__ __align__(128) __nv_bfloat16 g_Qc[(size_t)64 * SEQ * 128];   // [bh, s, hi(64)|lo(64)]
__device__ __align__(128) __nv_bfloat16 g_Kc[(size_t)64 * SEQ * 128];
__device__ __align__(128) __nv_bfloat16 g_Vt[(size_t)64 * 2 * HD * SEQ];// [bh, {hi,lo}, d, s]
__device__ __align__(128) __nv_bfloat16 g_Zc[(size_t)MR * 2048];        // [MR, hi|lo]

// ---------------------------------------------------------------------------
// Helpers
// ---------------------------------------------------------------------------
__device__ __forceinline__ uint32_t smem_u32(const void* p) {
    uint32_t a;
    asm("{ .reg .u64 t; cvta.to.shared.u64 t, %1; cvt.u32.u64 %0, t; }" : "=r"(a) : "l"(p));
    return a;
}
#define SWZ(o) ((o) ^ (((o) >> 3) & 0x70))
#define CP16(dst, src) asm volatile("cp.async.cg.shared.global [%0], [%1], 16;" :: "r"(dst), "l"(src))
#define CP_COMMIT() asm volatile("cp.async.commit_group;" ::: "memory")
#define CP_WAIT0()  asm volatile("cp.async.wait_group 0;" ::: "memory")
#define CP_WAIT1()  asm volatile("cp.async.wait_group 1;" ::: "memory")

#define LDMX4(r, addr) asm volatile( \
    "ldmatrix.sync.aligned.m8n8.x4.shared.b16 {%0,%1,%2,%3}, [%4];" \
    : "=r"((r)[0]), "=r"((r)[1]), "=r"((r)[2]), "=r"((r)[3]) : "r"(addr))

#define MMA16816(c, a, b0, b1) asm volatile( \
    "mma.sync.aligned.m16n8k16.row.col.f32.bf16.bf16.f32 " \
    "{%0,%1,%2,%3},{%4,%5,%6,%7},{%8,%9},{%0,%1,%2,%3};" \
    : "+f"((c)[0]), "+f"((c)[1]), "+f"((c)[2]), "+f"((c)[3]) \
    : "r"((a)[0]), "r"((a)[1]), "r"((a)[2]), "r"((a)[3]), "r"(b0), "r"(b1))

// fast e^x on FMA pipe (x <= 0), rel err ~2e-5
__device__ __forceinline__ float fexp(float x) {
    float t = fmaxf(x * 1.4426950408889634f, -80.f);
    float fl = floorf(t);
    float f = t - fl;
    float p = fmaf(f, 1.5403530393e-4f, 1.3333558146e-3f);
    p = fmaf(p, f, 9.6181291076e-3f);
    p = fmaf(p, f, 5.5504108664e-2f);
    p = fmaf(p, f, 2.4022650696e-1f);
    p = fmaf(p, f, 6.9314718056e-1f);
    p = fmaf(p, f, 1.0f);
    return p * __int_as_float(((int)fl + 127) << 23);
}
__device__ __forceinline__ void hilo(float v, __nv_bfloat16& h, __nv_bfloat16& l) {
    h = __float2bfloat16(v);
    l = __float2bfloat16(v - __bfloat162float(h));
}
__device__ __forceinline__ uint32_t pack2(float x, float y) {   // x -> low half
    __nv_bfloat162 t = __floats2bfloat162_rn(x, y);
    return *(uint32_t*)&t;
}

// ---------------------------------------------------------------------------
// Converters
// ---------------------------------------------------------------------------
__global__ void conv_x(const float* __restrict__ X, __nv_bfloat16* __restrict__ Xc) {
    int i = blockIdx.x * 256 + threadIdx.x;
    float4 v = ((const float4*)X)[i];
    int row = i >> 8;
    int c = (i & 255) * 4;
    __nv_bfloat16 h, l;
    size_t b = (size_t)row * 2048 + c;
    hilo(v.x, h, l); Xc[b + 0] = h; Xc[b + 1024 + 0] = l;
    hilo(v.y, h, l); Xc[b + 1] = h; Xc[b + 1024 + 1] = l;
    hilo(v.z, h, l); Xc[b + 2] = h; Xc[b + 1024 + 2] = l;
    hilo(v.w, h, l); Xc[b + 3] = h; Xc[b + 1024 + 3] = l;
}
__global__ void conv_w(const float* __restrict__ W, __nv_bfloat16* __restrict__ Wct) {
    __shared__ float t[32][33];
    int bx = blockIdx.x * 32, by = blockIdx.y * 32;  // bx: k, by: n
    int x = threadIdx.x & 31, y = threadIdx.x >> 5;
    #pragma unroll
    for (int i = 0; i < 32; i += 8) t[y + i][x] = W[(size_t)(bx + y + i) * 1024 + by + x];
    __syncthreads();
    #pragma unroll
    for (int i = 0; i < 32; i += 8) {
        float v = t[x][y + i];                        // W[bx+x, by+y+i]
        __nv_bfloat16 h, l; hilo(v, h, l);
        size_t n = by + y + i, k = bx + x;
        Wct[n * 2048 + k] = h;
        Wct[n * 2048 + 1024 + k] = l;
    }
}

// ---------------------------------------------------------------------------
// mma.sync GEMM: D[8192,1024] = Xc(cat) @ Wct(cat)^T + bias, tile 128x128, BK=64
// A cat = [hi|lo|hi] (3072), B cat = [hi|hi|lo]; dedup via k index mapping.
// MODE 0: head-cat bf16 (Q/K)   MODE 1: transposed V hi/lo   MODE 2: fp32 out
// ---------------------------------------------------------------------------
template <int MODE>
__global__ void __launch_bounds__(256)
gemm_cat(const __nv_bfloat16* __restrict__ A, const __nv_bfloat16* __restrict__ Bw,
         const float* __restrict__ bias, void* __restrict__ Cout)
{
    extern __shared__ char dsm[];
    const uint32_t sb = (smem_u32(dsm) + 1023u) & ~1023u;
    const int tid = threadIdx.x, w = tid >> 5, lane = tid & 31;
    const int wm = w & 3, wn = w >> 2;
    const int m0 = blockIdx.y * 128, n0 = blockIdx.x * 128;

    auto load_chunk = [&](int c, int buf) {
        int kk = c * 64;
        int ka = kk < 2048 ? kk : kk - 2048;        // A: [hi|lo|hi]
        int kb = kk < 1024 ? kk : kk - 1024;        // B: [hi|hi|lo]
        uint32_t ab = sb + buf * 32768, bb = ab + 16384;
        #pragma unroll
        for (int i = 0; i < 4; i++) {
            int u = tid + i * 256, row = u >> 3, sl = u & 7;
            CP16(ab + SWZ(row * 128 + sl * 16), A + (size_t)(m0 + row) * 2048 + ka + sl * 8);
            CP16(bb + SWZ(row * 128 + sl * 16), Bw + (size_t)(n0 + row) * 2048 + kb + sl * 8);
        }
    };

    float acc[2][8][4];
    #pragma unroll
    for (int mt = 0; mt < 2; mt++)
        #pragma unroll
        for (int nt = 0; nt < 8; nt++)
            #pragma unroll
            for (int r = 0; r < 4; r++) acc[mt][nt][r] = 0.f;

    const int NC = 48;
    load_chunk(0, 0); CP_COMMIT();
    for (int c = 0; c < NC; c++) {
        if (c + 1 < NC) { load_chunk(c + 1, (c + 1) & 1); CP_COMMIT(); CP_WAIT1(); }
        else CP_WAIT0();
        __syncthreads();
        const uint32_t ab = sb + (c & 1) * 32768, bb = ab + 16384;
        #pragma unroll
        for (int kk = 0; kk < 4; kk++) {
            uint32_t a[2][4];
            #pragma unroll
            for (int mt = 0; mt < 2; mt++)
                LDMX4(a[mt], ab + SWZ((wm * 32 + mt * 16 + (lane & 15)) * 128
                                      + kk * 32 + (lane >> 4) * 16));
            #pragma unroll
            for (int p = 0; p < 4; p++) {
                uint32_t b[4];
                LDMX4(b, bb + SWZ((wn * 64 + p * 16 + ((lane >> 4) << 3) + (lane & 7)) * 128
                                  + kk * 32 + ((lane >> 3) & 1) * 16));
                #pragma unroll
                for (int mt = 0; mt < 2; mt++) {
                    MMA16816(acc[mt][2 * p],     a[mt], b[0], b[1]);
                    MMA16816(acc[mt][2 * p + 1], a[mt], b[2], b[3]);
                }
            }
        }
        __syncthreads();
    }

    // epilogue
    #pragma unroll
    for (int mt = 0; mt < 2; mt++)
        #pragma unroll
        for (int nt = 0; nt < 8; nt++)
            #pragma unroll
            for (int r = 0; r < 4; r++) {
                int row = m0 + wm * 32 + mt * 16 + (lane >> 2) + (r >> 1) * 8;
                int col = n0 + wn * 64 + nt * 8 + (lane & 3) * 2 + (r & 1);
                float val = acc[mt][nt][r] + bias[col];
                if (MODE == 2) {
                    ((float*)Cout)[(size_t)row * 1024 + col] = val;
                } else {
                    __nv_bfloat16 h, l; hilo(val, h, l);
                    int bh = (row >> 11) * 16 + (col >> 6), s = row & 2047, d = col & 63;
                    __nv_bfloat16* C = (__nv_bfloat16*)Cout;
                    if (MODE == 0) {
                        size_t o = ((size_t)bh * 2048 + s) * 128 + d;
                        C[o] = h; C[o + 64] = l;
                    } else {
                        C[((size_t)(bh * 2 + 0) * 64 + d) * 2048 + s] = h;
                        C[((size_t)(bh * 2 + 1) * 64 + d) * 2048 + s] = l;
                    }
                }
            }
}

// ---------------------------------------------------------------------------
// Flash attention via mma.sync: CTA = (qb, bh): 128 q-rows x 128-key blocks.
// 8 warps; each warp owns 16 full q-rows -> softmax warp-local, P stays in
// registers (scores C-fragment == PV A-fragment).
// smem: Q (32KB, resident) | K (32KB) | V hi/lo (32KB)
// ---------------------------------------------------------------------------
__global__ void __launch_bounds__(256, 1)
attn_mma(const __nv_bfloat16* __restrict__ Qc, const __nv_bfloat16* __restrict__ Kc,
         const __nv_bfloat16* __restrict__ Vt, __nv_bfloat16* __restrict__ Zc)
{
    extern __shared__ char dsm[];
    const uint32_t sb = (smem_u32(dsm) + 1023u) & ~1023u;
    const uint32_t Qs = sb, Ks = sb + 32768, Vs = sb + 65536;
    const int tid = threadIdx.x, w = tid >> 5, lane = tid & 31;
    const int qb = blockIdx.x, bh = blockIdx.y;

    // ---- load Q tile (128 rows x 256B), resident ----
    {
        const size_t qbase = ((size_t)bh * 2048 + qb * 128) * 128;
        #pragma unroll
        for (int i = 0; i < 8; i++) {
            int u = tid + i * 256, row = u >> 4, seg = u & 15;
            CP16(Qs + SWZ((row * 2 + (seg >> 3)) * 128 + (seg & 7) * 16),
                 Qc + qbase + (size_t)row * 128 + seg * 8);
        }
        CP_COMMIT(); CP_WAIT0();
    }
    __syncthreads();

    // ---- Q A-fragments: 8 k16 tiles (hi 0-3, lo 4-7), resident ----
    uint32_t aQ[8][4];
    #pragma unroll
    for (int t = 0; t < 8; t++)
        LDMX4(aQ[t], Qs + SWZ(((w * 16 + (lane & 15)) * 2 + (t >> 2)) * 128
                              + (t & 3) * 32 + (lane >> 4) * 16));

    float mrow[2] = {-1e30f, -1e30f}, lrow[2] = {0.f, 0.f};
    float o[8][4];
    #pragma unroll
    for (int t = 0; t < 8; t++)
        #pragma unroll
        for (int r = 0; r < 4; r++) o[t][r] = 0.f;

    for (int kb = 0; kb < 16; kb++) {
        __syncthreads();   // prior iter's ldmatrix reads of K/V complete
        {
            const size_t kbase = ((size_t)bh * 2048 + kb * 128) * 128;
            #pragma unroll
            for (int i = 0; i < 8; i++) {
                int u = tid + i * 256, row = u >> 4, seg = u & 15;
                CP16(Ks + SWZ((row * 2 + (seg >> 3)) * 128 + (seg & 7) * 16),
                     Kc + kbase + (size_t)row * 128 + seg * 8);
            }
            #pragma unroll
            for (int i = 0; i < 8; i++) {
                int u = tid + i * 256, part = u >> 10, v = u & 1023;
                int d = v >> 4, seg = v & 15;
                CP16(Vs + part * 16384 + SWZ((d * 2 + (seg >> 3)) * 128 + (seg & 7) * 16),
                     Vt + ((size_t)(bh * 2 + part) * 64 + d) * 2048 + kb * 128 + seg * 8);
            }
            CP_COMMIT(); CP_WAIT0();
        }
        __syncthreads();

        // ---- scores: 16 rows x 128 keys, K' = 192 ([Qhi Khi][Qlo Khi][Qhi Klo])
        float s[16][4];
        #pragma unroll
        for (int nt = 0; nt < 16; nt++)
            #pragma unroll
            for (int r = 0; r < 4; r++) s[nt][r] = 0.f;

        #pragma unroll
        for (int t = 0; t < 12; t++) {
            const uint32_t* a = aQ[t < 8 ? t : t - 8];
            const int khalf = (t >= 8) ? 1 : 0;
            const int kbyte = (t & 3) * 32;
            #pragma unroll
            for (int p = 0; p < 8; p++) {
                uint32_t b[4];
                LDMX4(b, Ks + SWZ(((p * 16 + ((lane >> 4) << 3) + (lane & 7)) * 2 + khalf) * 128
                                  + kbyte + ((lane >> 3) & 1) * 16));
                MMA16816(s[2 * p],     a, b[0], b[1]);
                MMA16816(s[2 * p + 1], a, b[2], b[3]);
            }
        }

        // ---- online softmax (per lane: rows g=0 -> lane/4, g=1 -> +8) ----
        float alpha[2];
        #pragma unroll
        for (int g = 0; g < 2; g++) {
            float pm = -1e30f;
            #pragma unroll
            for (int nt = 0; nt < 16; nt++) {
                s[nt][2 * g]     *= 0.125f;
                s[nt][2 * g + 1] *= 0.125f;
                pm = fmaxf(pm, fmaxf(s[nt][2 * g], s[nt][2 * g + 1]));
            }
            pm = fmaxf(pm, __shfl_xor_sync(0xffffffffu, pm, 1));
            pm = fmaxf(pm, __shfl_xor_sync(0xffffffffu, pm, 2));
            float mnew = fmaxf(mrow[g], pm);
            alpha[g] = fexp(mrow[g] - mnew);
            float sum = 0.f;
            #pragma unroll
            for (int nt = 0; nt < 16; nt++) {
                s[nt][2 * g]     = fexp(s[nt][2 * g] - mnew);
                s[nt][2 * g + 1] = fexp(s[nt][2 * g + 1] - mnew);
                sum += s[nt][2 * g] + s[nt][2 * g + 1];
            }
            sum += __shfl_xor_sync(0xffffffffu, sum, 1);
            sum += __shfl_xor_sync(0xffffffffu, sum, 2);
            lrow[g] = lrow[g] * alpha[g] + sum;
            mrow[g] = mnew;
        }
        // rescale O
        #pragma unroll
        for (int t = 0; t < 8; t++)
            #pragma unroll
            for (int r = 0; r < 4; r++) o[t][r] *= alpha[r >> 1];

        // ---- P -> bf16 hi/lo A-fragments (C-to-A register reuse) ----
        uint32_t ph[8][4], pl[8][4];
        #pragma unroll
        for (int u = 0; u < 8; u++) {
            #pragma unroll
            for (int q = 0; q < 4; q++) {
                // q=0: tile 2u regs 0,1 | q=1: tile 2u regs 2,3
                // q=2: tile 2u+1 regs 0,1 | q=3: tile 2u+1 regs 2,3
                const int nt = 2 * u + (q >> 1), rb = (q & 1) * 2;
                float x = s[nt][rb], y = s[nt][rb + 1];
                __nv_bfloat16 hx = __float2bfloat16(x), hy = __float2bfloat16(y);
                ph[u][q] = pack2(__bfloat162float(hx), __bfloat162float(hy));
                pl[u][q] = pack2(x - __bfloat162float(hx), y - __bfloat162float(hy));
            }
        }

        // ---- PV: O[16,64] += [Phi|Plo]·Vhi + Phi·Vlo ----
        #pragma unroll
        for (int u = 0; u < 8; u++) {
            const uint32_t vrow = (u >> 2) * 128;         // sblk offset within d-row
            const uint32_t vbyte = (u & 3) * 32 + ((lane >> 3) & 1) * 16;
            #pragma unroll
            for (int p = 0; p < 4; p++) {
                uint32_t b[4];
                const uint32_t drow = (p * 16 + ((lane >> 4) << 3) + (lane & 7)) * 256;
                LDMX4(b, Vs + SWZ(drow + vrow + vbyte));  // V hi (part 0)
                MMA16816(o[2 * p],     ph[u], b[0], b[1]);
                MMA16816(o[2 * p + 1], ph[u], b[2], b[3]);
                MMA16816(o[2 * p],     pl[u], b[0], b[1]);
                MMA16816(o[2 * p + 1], pl[u], b[2], b[3]);
                LDMX4(b, Vs + 16384 + SWZ(drow + vrow + vbyte));  // V lo (part 1)
                MMA16816(o[2 * p],     ph[u], b[0], b[1]);
                MMA16816(o[2 * p + 1], ph[u], b[2], b[3]);
            }
        }
    }

    // ---- finalize + write Zc [MR, hi(1024)|lo(1024)] ----
    const float inv0 = 1.f / lrow[0], inv1 = 1.f / lrow[1];
    const int b = bh >> 4, h = bh & 15;
    #pragma unroll
    for (int t = 0; t < 8; t++)
        #pragma unroll
        for (int r = 0; r < 4; r++) {
            int rl = w * 16 + (lane >> 2) + (r >> 1) * 8;
            int d  = t * 8 + (lane & 3) * 2 + (r & 1);
            float val = o[t][r] * ((r >> 1) ? inv1 : inv0);
            __nv_bfloat16 hi, lo; hilo(val, hi, lo);
            size_t idx = ((size_t)(b * 2048 + qb * 128 + rl)) * 2048 + h * 64 + d;
            Zc[idx] = hi;
            Zc[idx + 1024] = lo;
        }
}

// ---------------------------------------------------------------------------
// Host launcher
// ---------------------------------------------------------------------------
extern "C" void kernel_launch(void* const* d_in, const int* in_sizes, int n_in,
                              void* d_out, int out_size)
{
    const float* query = (const float*)d_in[0];
    const float* key   = (const float*)d_in[1];
    const float* value = (const float*)d_in[2];
    const float* Wq = (const float*)d_in[3];  const float* bq = (const float*)d_in[4];
    const float* Wk = (const float*)d_in[5];  const float* bk = (const float*)d_in[6];
    const float* Wv = (const float*)d_in[7];  const float* bv = (const float*)d_in[8];
    const float* Wo = (const float*)d_in[9];  const float* bo = (const float*)d_in[10];

    __nv_bfloat16 *Xc, *Wct, *Qc, *Kc, *Vt, *Zc;
    cudaGetSymbolAddress((void**)&Xc, g_Xc);
    cudaGetSymbolAddress((void**)&Wct, g_Wct);
    cudaGetSymbolAddress((void**)&Qc, g_Qc);
    cudaGetSymbolAddress((void**)&Kc, g_Kc);
    cudaGetSymbolAddress((void**)&Vt, g_Vt);
    cudaGetSymbolAddress((void**)&Zc, g_Zc);

    cudaFuncSetAttribute(gemm_cat<0>, cudaFuncAttributeMaxDynamicSharedMemorySize, 66560);
    cudaFuncSetAttribute(gemm_cat<1>, cudaFuncAttributeMaxDynamicSharedMemorySize, 66560);
    cudaFuncSetAttribute(gemm_cat<2>, cudaFuncAttributeMaxDynamicSharedMemorySize, 66560);
    cudaFuncSetAttribute(attn_mma, cudaFuncAttributeMaxDynamicSharedMemorySize, 99328);

    const dim3 gw(32, 32), gx(8192), gg(8, 64);

    conv_w<<<gw, 256>>>(Wq, Wct);
    conv_x<<<gx, 256>>>(query, Xc);
    gemm_cat<0><<<gg, 256, 66560>>>(Xc, Wct, bq, Qc);

    conv_w<<<gw, 256>>>(Wk, Wct);
    conv_x<<<gx, 256>>>(key, Xc);
    gemm_cat<0><<<gg, 256, 66560>>>(Xc, Wct, bk, Kc);

    conv_w<<<gw, 256>>>(Wv, Wct);
    conv_x<<<gx, 256>>>(value, Xc);
    gemm_cat<1><<<gg, 256, 66560>>>(Xc, Wct, bv, Vt);

    attn_mma<<<dim3(16, 64), 256, 99328>>>(Qc, Kc, Vt, Zc);

    conv_w<<<gw, 256>>>(Wo, Wct);
    gemm_cat<2><<<gg, 256, 66560>>>(Zc, Wct, bo, d_out);
}

// round 5
// speedup vs baseline: 2.8919x; 1.1464x over previous
#include <cuda_runtime.h>
#include <cuda_bf16.h>
#include <cstdint>

#define BATCH 4
#define SEQ   2048
#define DM    1024
#define NH    16
#define HD    64
#define MR    (BATCH*SEQ)   // 8192

// ---------------------------------------------------------------------------
// Scratch (__device__ globals: allocation-free rule)
// ---------------------------------------------------------------------------
__device__ __align__(128) __nv_bfloat16 g_Xc[3][(size_t)MR * 2048];     // q,k,v inputs [MR, hi|lo]
__device__ __align__(128) __nv_bfloat16 g_Wct[4][(size_t)1024 * 2048];  // Wq,Wk,Wv,Wo [n, hi|lo over k]
__device__ __align__(128) __nv_bfloat16 g_Qc[(size_t)64 * SEQ * 128];   // [bh, s, hi(64)|lo(64)]
__device__ __align__(128) __nv_bfloat16 g_Kc[(size_t)64 * SEQ * 128];
__device__ __align__(128) __nv_bfloat16 g_Vt[(size_t)64 * 2 * HD * SEQ];// [bh, {hi,lo}, d, s]
__device__ __align__(128) __nv_bfloat16 g_Zc[(size_t)MR * 2048];        // [MR, hi|lo]

// ---------------------------------------------------------------------------
// Helpers
// ---------------------------------------------------------------------------
__device__ __forceinline__ uint32_t smem_u32(const void* p) {
    uint32_t a;
    asm("{ .reg .u64 t; cvta.to.shared.u64 t, %1; cvt.u32.u64 %0, t; }" : "=r"(a) : "l"(p));
    return a;
}
#define SWZ(o) ((o) ^ (((o) >> 3) & 0x70))
#define CP16(dst, src) asm volatile("cp.async.cg.shared.global [%0], [%1], 16;" :: "r"(dst), "l"(src))
#define CP_COMMIT() asm volatile("cp.async.commit_group;" ::: "memory")
#define CP_WAIT0()  asm volatile("cp.async.wait_group 0;" ::: "memory")
#define CP_WAIT1()  asm volatile("cp.async.wait_group 1;" ::: "memory")
#define CP_WAIT2()  asm volatile("cp.async.wait_group 2;" ::: "memory")

#define LDMX4(r, addr) asm volatile( \
    "ldmatrix.sync.aligned.m8n8.x4.shared.b16 {%0,%1,%2,%3}, [%4];" \
    : "=r"((r)[0]), "=r"((r)[1]), "=r"((r)[2]), "=r"((r)[3]) : "r"(addr))

#define MMA16816(c, a, b0, b1) asm volatile( \
    "mma.sync.aligned.m16n8k16.row.col.f32.bf16.bf16.f32 " \
    "{%0,%1,%2,%3},{%4,%5,%6,%7},{%8,%9},{%0,%1,%2,%3};" \
    : "+f"((c)[0]), "+f"((c)[1]), "+f"((c)[2]), "+f"((c)[3]) \
    : "r"((a)[0]), "r"((a)[1]), "r"((a)[2]), "r"((a)[3]), "r"(b0), "r"(b1))

// fast e^x on FMA pipe (x <= 0), rel err ~2e-5
__device__ __forceinline__ float fexp(float x) {
    float t = fmaxf(x * 1.4426950408889634f, -80.f);
    float fl = floorf(t);
    float f = t - fl;
    float p = fmaf(f, 1.5403530393e-4f, 1.3333558146e-3f);
    p = fmaf(p, f, 9.6181291076e-3f);
    p = fmaf(p, f, 5.5504108664e-2f);
    p = fmaf(p, f, 2.4022650696e-1f);
    p = fmaf(p, f, 6.9314718056e-1f);
    p = fmaf(p, f, 1.0f);
    return p * __int_as_float(((int)fl + 127) << 23);
}
__device__ __forceinline__ void hilo(float v, __nv_bfloat16& h, __nv_bfloat16& l) {
    h = __float2bfloat16(v);
    l = __float2bfloat16(v - __bfloat162float(h));
}
__device__ __forceinline__ uint32_t pack2(float x, float y) {   // x -> low half
    __nv_bfloat162 t = __floats2bfloat162_rn(x, y);
    return *(uint32_t*)&t;
}

// ---------------------------------------------------------------------------
// Converters (fused: all inputs / all weights in one launch each)
// ---------------------------------------------------------------------------
__global__ void conv_x3(const float* __restrict__ X0, const float* __restrict__ X1,
                        const float* __restrict__ X2) {
    const float* X = blockIdx.y == 0 ? X0 : (blockIdx.y == 1 ? X1 : X2);
    __nv_bfloat16* Xc = g_Xc[blockIdx.y];
    int i = blockIdx.x * 256 + threadIdx.x;
    float4 v = ((const float4*)X)[i];
    int row = i >> 8;
    int c = (i & 255) * 4;
    __nv_bfloat16 h, l;
    size_t b = (size_t)row * 2048 + c;
    hilo(v.x, h, l); Xc[b + 0] = h; Xc[b + 1024 + 0] = l;
    hilo(v.y, h, l); Xc[b + 1] = h; Xc[b + 1024 + 1] = l;
    hilo(v.z, h, l); Xc[b + 2] = h; Xc[b + 1024 + 2] = l;
    hilo(v.w, h, l); Xc[b + 3] = h; Xc[b + 1024 + 3] = l;
}
__global__ void conv_w4(const float* __restrict__ W0, const float* __restrict__ W1,
                        const float* __restrict__ W2, const float* __restrict__ W3) {
    const float* W = blockIdx.z == 0 ? W0 : (blockIdx.z == 1 ? W1 :
                     (blockIdx.z == 2 ? W2 : W3));
    __nv_bfloat16* Wct = g_Wct[blockIdx.z];
    __shared__ float t[32][33];
    int bx = blockIdx.x * 32, by = blockIdx.y * 32;  // bx: k, by: n
    int x = threadIdx.x & 31, y = threadIdx.x >> 5;
    #pragma unroll
    for (int i = 0; i < 32; i += 8) t[y + i][x] = W[(size_t)(bx + y + i) * 1024 + by + x];
    __syncthreads();
    #pragma unroll
    for (int i = 0; i < 32; i += 8) {
        float v = t[x][y + i];                        // W[bx+x, by+y+i]
        __nv_bfloat16 h, l; hilo(v, h, l);
        size_t n = by + y + i, k = bx + x;
        Wct[n * 2048 + k] = h;
        Wct[n * 2048 + 1024 + k] = l;
    }
}

// ---------------------------------------------------------------------------
// mma.sync GEMM: D[8192,1024] = Xc(cat) @ Wct(cat)^T + bias, tile 128x128,
// BK=64, 3-stage cp.async pipeline.
// A cat = [hi|lo|hi] (3072), B cat = [hi|hi|lo]; dedup via k index mapping.
// MODE 0: head-cat bf16 (Q/K)   MODE 1: transposed V hi/lo   MODE 2: fp32 out
// ---------------------------------------------------------------------------
template <int MODE>
__global__ void __launch_bounds__(256)
gemm_cat(const __nv_bfloat16* __restrict__ A, const __nv_bfloat16* __restrict__ Bw,
         const float* __restrict__ bias, void* __restrict__ Cout)
{
    extern __shared__ char dsm[];
    const uint32_t sb = (smem_u32(dsm) + 1023u) & ~1023u;
    const int tid = threadIdx.x, w = tid >> 5, lane = tid & 31;
    const int wm = w & 3, wn = w >> 2;
    const int m0 = blockIdx.y * 128, n0 = blockIdx.x * 128;

    auto load_chunk = [&](int c, int buf) {
        int kk = c * 64;
        int ka = kk < 2048 ? kk : kk - 2048;        // A: [hi|lo|hi]
        int kb = kk < 1024 ? kk : kk - 1024;        // B: [hi|hi|lo]
        uint32_t ab = sb + buf * 32768, bb = ab + 16384;
        #pragma unroll
        for (int i = 0; i < 4; i++) {
            int u = tid + i * 256, row = u >> 3, sl = u & 7;
            CP16(ab + SWZ(row * 128 + sl * 16), A + (size_t)(m0 + row) * 2048 + ka + sl * 8);
            CP16(bb + SWZ(row * 128 + sl * 16), Bw + (size_t)(n0 + row) * 2048 + kb + sl * 8);
        }
    };

    float acc[2][8][4];
    #pragma unroll
    for (int mt = 0; mt < 2; mt++)
        #pragma unroll
        for (int nt = 0; nt < 8; nt++)
            #pragma unroll
            for (int r = 0; r < 4; r++) acc[mt][nt][r] = 0.f;

    const int NC = 48;
    load_chunk(0, 0); CP_COMMIT();
    load_chunk(1, 1); CP_COMMIT();
    for (int c = 0; c < NC; c++) {
        if (c + 2 < NC)      { load_chunk(c + 2, (c + 2) % 3); CP_COMMIT(); CP_WAIT2(); }
        else if (c + 1 < NC) CP_WAIT1();
        else                 CP_WAIT0();
        __syncthreads();
        const uint32_t ab = sb + (c % 3) * 32768, bb = ab + 16384;
        #pragma unroll
        for (int kk = 0; kk < 4; kk++) {
            uint32_t a[2][4];
            #pragma unroll
            for (int mt = 0; mt < 2; mt++)
                LDMX4(a[mt], ab + SWZ((wm * 32 + mt * 16 + (lane & 15)) * 128
                                      + kk * 32 + (lane >> 4) * 16));
            #pragma unroll
            for (int p = 0; p < 4; p++) {
                uint32_t b[4];
                LDMX4(b, bb + SWZ((wn * 64 + p * 16 + ((lane >> 4) << 3) + (lane & 7)) * 128
                                  + kk * 32 + ((lane >> 3) & 1) * 16));
                #pragma unroll
                for (int mt = 0; mt < 2; mt++) {
                    MMA16816(acc[mt][2 * p],     a[mt], b[0], b[1]);
                    MMA16816(acc[mt][2 * p + 1], a[mt], b[2], b[3]);
                }
            }
        }
        __syncthreads();
    }

    // epilogue
    #pragma unroll
    for (int mt = 0; mt < 2; mt++)
        #pragma unroll
        for (int nt = 0; nt < 8; nt++)
            #pragma unroll
            for (int r = 0; r < 4; r++) {
                int row = m0 + wm * 32 + mt * 16 + (lane >> 2) + (r >> 1) * 8;
                int col = n0 + wn * 64 + nt * 8 + (lane & 3) * 2 + (r & 1);
                float val = acc[mt][nt][r] + bias[col];
                if (MODE == 2) {
                    ((float*)Cout)[(size_t)row * 1024 + col] = val;
                } else {
                    __nv_bfloat16 h, l; hilo(val, h, l);
                    int bh = (row >> 11) * 16 + (col >> 6), s = row & 2047, d = col & 63;
                    __nv_bfloat16* C = (__nv_bfloat16*)Cout;
                    if (MODE == 0) {
                        size_t o = ((size_t)bh * 2048 + s) * 128 + d;
                        C[o] = h; C[o + 64] = l;
                    } else {
                        C[((size_t)(bh * 2 + 0) * 64 + d) * 2048 + s] = h;
                        C[((size_t)(bh * 2 + 1) * 64 + d) * 2048 + s] = l;
                    }
                }
            }
}

// ---------------------------------------------------------------------------
// Flash attention via mma.sync: CTA = (qb, bh): 128 q-rows x 128-key blocks.
// 8 warps, each owns 16 full q-rows (softmax warp-local, P in registers).
// Double-buffered K/V: smem = Q(32K) | buf0(K 32K, V 32K) | buf1(64K) = 160K.
// ---------------------------------------------------------------------------
#define ATTN_SMEM (1024 + 32768 + 2 * 65536)

__global__ void __launch_bounds__(256, 1)
attn_mma(const __nv_bfloat16* __restrict__ Qc, const __nv_bfloat16* __restrict__ Kc,
         const __nv_bfloat16* __restrict__ Vt, __nv_bfloat16* __restrict__ Zc)
{
    extern __shared__ char dsm[];
    const uint32_t sb = (smem_u32(dsm) + 1023u) & ~1023u;
    const uint32_t Qs = sb;
    const int tid = threadIdx.x, w = tid >> 5, lane = tid & 31;
    const int qb = blockIdx.x, bh = blockIdx.y;

    auto load_kv = [&](int kb, uint32_t buf) {
        const uint32_t Ks = buf, Vs = buf + 32768;
        const size_t kbase = ((size_t)bh * 2048 + kb * 128) * 128;
        #pragma unroll
        for (int i = 0; i < 8; i++) {
            int u = tid + i * 256, row = u >> 4, seg = u & 15;
            CP16(Ks + SWZ((row * 2 + (seg >> 3)) * 128 + (seg & 7) * 16),
                 Kc + kbase + (size_t)row * 128 + seg * 8);
        }
        #pragma unroll
        for (int i = 0; i < 8; i++) {
            int u = tid + i * 256, part = u >> 10, v = u & 1023;
            int d = v >> 4, seg = v & 15;
            CP16(Vs + part * 16384 + SWZ((d * 2 + (seg >> 3)) * 128 + (seg & 7) * 16),
                 Vt + ((size_t)(bh * 2 + part) * 64 + d) * 2048 + kb * 128 + seg * 8);
        }
    };

    // ---- preamble: Q load + first K/V block in flight ----
    {
        const size_t qbase = ((size_t)bh * 2048 + qb * 128) * 128;
        #pragma unroll
        for (int i = 0; i < 8; i++) {
            int u = tid + i * 256, row = u >> 4, seg = u & 15;
            CP16(Qs + SWZ((row * 2 + (seg >> 3)) * 128 + (seg & 7) * 16),
                 Qc + qbase + (size_t)row * 128 + seg * 8);
        }
        CP_COMMIT();
    }
    load_kv(0, sb + 32768); CP_COMMIT();
    CP_WAIT1();              // Q done; kv0 still in flight
    __syncthreads();

    // ---- Q A-fragments: 8 k16 tiles (hi 0-3, lo 4-7), resident ----
    uint32_t aQ[8][4];
    #pragma unroll
    for (int t = 0; t < 8; t++)
        LDMX4(aQ[t], Qs + SWZ(((w * 16 + (lane & 15)) * 2 + (t >> 2)) * 128
                              + (t & 3) * 32 + (lane >> 4) * 16));

    float mrow[2] = {-1e30f, -1e30f}, lrow[2] = {0.f, 0.f};
    float o[8][4];
    #pragma unroll
    for (int t = 0; t < 8; t++)
        #pragma unroll
        for (int r = 0; r < 4; r++) o[t][r] = 0.f;

    for (int kb = 0; kb < 16; kb++) {
        __syncthreads();   // all warps done reading buf[(kb+1)&1] (iter kb-1)
        if (kb + 1 < 16) { load_kv(kb + 1, sb + 32768 + ((kb + 1) & 1) * 65536);
                           CP_COMMIT(); CP_WAIT1(); }
        else CP_WAIT0();
        __syncthreads();   // buf[kb&1] ready for all
        const uint32_t Ks = sb + 32768 + (kb & 1) * 65536, Vs = Ks + 32768;

        // ---- scores: 16 rows x 128 keys, K' = 192 ([Qhi Khi][Qlo Khi][Qhi Klo])
        float s[16][4];
        #pragma unroll
        for (int nt = 0; nt < 16; nt++)
            #pragma unroll
            for (int r = 0; r < 4; r++) s[nt][r] = 0.f;

        #pragma unroll
        for (int t = 0; t < 12; t++) {
            const uint32_t* a = aQ[t < 8 ? t : t - 8];
            const int khalf = (t >= 8) ? 1 : 0;
            const int kbyte = (t & 3) * 32;
            #pragma unroll
            for (int p = 0; p < 8; p++) {
                uint32_t b[4];
                LDMX4(b, Ks + SWZ(((p * 16 + ((lane >> 4) << 3) + (lane & 7)) * 2 + khalf) * 128
                                  + kbyte + ((lane >> 3) & 1) * 16));
                MMA16816(s[2 * p],     a, b[0], b[1]);
                MMA16816(s[2 * p + 1], a, b[2], b[3]);
            }
        }

        // ---- online softmax (per lane: rows g=0 -> lane/4, g=1 -> +8) ----
        float alpha[2];
        #pragma unroll
        for (int g = 0; g < 2; g++) {
            float pm = -1e30f;
            #pragma unroll
            for (int nt = 0; nt < 16; nt++) {
                s[nt][2 * g]     *= 0.125f;
                s[nt][2 * g + 1] *= 0.125f;
                pm = fmaxf(pm, fmaxf(s[nt][2 * g], s[nt][2 * g + 1]));
            }
            pm = fmaxf(pm, __shfl_xor_sync(0xffffffffu, pm, 1));
            pm = fmaxf(pm, __shfl_xor_sync(0xffffffffu, pm, 2));
            float mnew = fmaxf(mrow[g], pm);
            alpha[g] = fexp(mrow[g] - mnew);
            float sum = 0.f;
            #pragma unroll
            for (int nt = 0; nt < 16; nt++) {
                s[nt][2 * g]     = fexp(s[nt][2 * g] - mnew);
                s[nt][2 * g + 1] = fexp(s[nt][2 * g + 1] - mnew);
                sum += s[nt][2 * g] + s[nt][2 * g + 1];
            }
            sum += __shfl_xor_sync(0xffffffffu, sum, 1);
            sum += __shfl_xor_sync(0xffffffffu, sum, 2);
            lrow[g] = lrow[g] * alpha[g] + sum;
            mrow[g] = mnew;
        }
        // rescale O
        #pragma unroll
        for (int t = 0; t < 8; t++)
            #pragma unroll
            for (int r = 0; r < 4; r++) o[t][r] *= alpha[r >> 1];

        // ---- PV: O[16,64] += [Phi|Plo]·Vhi + Phi·Vlo ----
        // P hi/lo A-fragments built per-u (keeps register live range small)
        #pragma unroll
        for (int u = 0; u < 8; u++) {
            uint32_t ph[4], pl[4];
            #pragma unroll
            for (int q = 0; q < 4; q++) {
                const int nt = 2 * u + (q >> 1), rb = (q & 1) * 2;
                float x = s[nt][rb], y = s[nt][rb + 1];
                __nv_bfloat16 hx = __float2bfloat16(x), hy = __float2bfloat16(y);
                ph[q] = pack2(__bfloat162float(hx), __bfloat162float(hy));
                pl[q] = pack2(x - __bfloat162float(hx), y - __bfloat162float(hy));
            }
            const uint32_t vrow = (u >> 2) * 128;
            const uint32_t vbyte = (u & 3) * 32 + ((lane >> 3) & 1) * 16;
            #pragma unroll
            for (int p = 0; p < 4; p++) {
                uint32_t b[4];
                const uint32_t drow = (p * 16 + ((lane >> 4) << 3) + (lane & 7)) * 256;
                LDMX4(b, Vs + SWZ(drow + vrow + vbyte));            // V hi
                MMA16816(o[2 * p],     ph, b[0], b[1]);
                MMA16816(o[2 * p + 1], ph, b[2], b[3]);
                MMA16816(o[2 * p],     pl, b[0], b[1]);
                MMA16816(o[2 * p + 1], pl, b[2], b[3]);
                LDMX4(b, Vs + 16384 + SWZ(drow + vrow + vbyte));    // V lo
                MMA16816(o[2 * p],     ph, b[0], b[1]);
                MMA16816(o[2 * p + 1], ph, b[2], b[3]);
            }
        }
    }

    // ---- finalize + write Zc [MR, hi(1024)|lo(1024)] ----
    const float inv0 = 1.f / lrow[0], inv1 = 1.f / lrow[1];
    const int b = bh >> 4, h = bh & 15;
    #pragma unroll
    for (int t = 0; t < 8; t++)
        #pragma unroll
        for (int r = 0; r < 4; r++) {
            int rl = w * 16 + (lane >> 2) + (r >> 1) * 8;
            int d  = t * 8 + (lane & 3) * 2 + (r & 1);
            float val = o[t][r] * ((r >> 1) ? inv1 : inv0);
            __nv_bfloat16 hi, lo; hilo(val, hi, lo);
            size_t idx = ((size_t)(b * 2048 + qb * 128 + rl)) * 2048 + h * 64 + d;
            Zc[idx] = hi;
            Zc[idx + 1024] = lo;
        }
}

// ---------------------------------------------------------------------------
// Host launcher
// ---------------------------------------------------------------------------
extern "C" void kernel_launch(void* const* d_in, const int* in_sizes, int n_in,
                              void* d_out, int out_size)
{
    const float* query = (const float*)d_in[0];
    const float* key   = (const float*)d_in[1];
    const float* value = (const float*)d_in[2];
    const float* Wq = (const float*)d_in[3];  const float* bq = (const float*)d_in[4];
    const float* Wk = (const float*)d_in[5];  const float* bk = (const float*)d_in[6];
    const float* Wv = (const float*)d_in[7];  const float* bv = (const float*)d_in[8];
    const float* Wo = (const float*)d_in[9];  const float* bo = (const float*)d_in[10];

    __nv_bfloat16 *Xc, *Wct, *Qc, *Kc, *Vt, *Zc;
    cudaGetSymbolAddress((void**)&Xc, g_Xc);
    cudaGetSymbolAddress((void**)&Wct, g_Wct);
    cudaGetSymbolAddress((void**)&Qc, g_Qc);
    cudaGetSymbolAddress((void**)&Kc, g_Kc);
    cudaGetSymbolAddress((void**)&Vt, g_Vt);
    cudaGetSymbolAddress((void**)&Zc, g_Zc);
    const size_t XN = (size_t)MR * 2048, WN = (size_t)1024 * 2048;

    cudaFuncSetAttribute(gemm_cat<0>, cudaFuncAttributeMaxDynamicSharedMemorySize, 99328);
    cudaFuncSetAttribute(gemm_cat<1>, cudaFuncAttributeMaxDynamicSharedMemorySize, 99328);
    cudaFuncSetAttribute(gemm_cat<2>, cudaFuncAttributeMaxDynamicSharedMemorySize, 99328);
    cudaFuncSetAttribute(attn_mma, cudaFuncAttributeMaxDynamicSharedMemorySize, ATTN_SMEM);

    const dim3 gg(8, 64);

    conv_w4<<<dim3(32, 32, 4), 256>>>(Wq, Wk, Wv, Wo);
    conv_x3<<<dim3(8192, 3), 256>>>(query, key, value);

    gemm_cat<0><<<gg, 256, 99328>>>(Xc,          Wct,          bq, Qc);
    gemm_cat<0><<<gg, 256, 99328>>>(Xc + XN,     Wct + WN,     bk, Kc);
    gemm_cat<1><<<gg, 256, 99328>>>(Xc + 2 * XN, Wct + 2 * WN, bv, Vt);

    attn_mma<<<dim3(16, 64), 256, ATTN_SMEM>>>(Qc, Kc, Vt, Zc);

    gemm_cat<2><<<gg, 256, 99328>>>(Zc, Wct + 3 * WN, bo, d_out);
}